// round 5
// baseline (speedup 1.0000x reference)
#include <cuda_runtime.h>
#include <cuda_bf16.h>

// ElasticEnergyLossWithJacobian — GB300 sm_103a
// Input: deformation_field (2,3,192,192,192) fp32. Output: scalar fp32.
// Strategy: one fused stencil+reduction pass. Each thread handles a float4
// (4 consecutive z voxels). x/y neighbors via direct vectorized loads (L1/L2
// cached; adjacent rows reuse lines), z neighbors via the center float4 plus
// two halo scalars. Single combined sum: mean(energy + 0.1*relu(-jac)).

#define DD 192
#define S1 192
#define S2 (192*192)
#define S3 ((long)192*192*192)
#define NVOX (2.0*192.0*192.0*192.0)

__device__ double g_accum;

__device__ __forceinline__ float robust01(float x) {
    // delta = 0.01
    float a = fabsf(x);
    return (a <= 0.01f) ? 0.5f * x * x : 0.01f * (a - 0.005f);
}

__global__ void zero_kernel() { g_accum = 0.0; }

__global__ __launch_bounds__(192) void elastic_kernel(const float* __restrict__ df) {
    // grid: 2 * 192 * 48 blocks; block = (48 z-quads, 4 y rows)
    int bid = blockIdx.x;
    int yt = bid % 48;
    int x  = (bid / 48) % DD;
    int b  = bid / (48 * DD);
    int y  = yt * 4 + threadIdx.y;
    int z4 = threadIdx.x * 4;

    const float* base = df + (long)b * 3 * S3;

    long co  = (long)x * S2 + (long)y * S1 + z4;
    long cxm = (long)max(x - 1, 0)   * S2 + (long)y * S1 + z4;
    long cxp = (long)min(x + 1, DD-1) * S2 + (long)y * S1 + z4;
    long cym = (long)x * S2 + (long)max(y - 1, 0)    * S1 + z4;
    long cyp = (long)x * S2 + (long)min(y + 1, DD-1) * S1 + z4;

    float sx = (x == 0 || x == DD-1) ? 1.0f : 0.5f;
    float sy = (y == 0 || y == DD-1) ? 1.0f : 0.5f;

    float dX[3][4], dY[3][4], dZ[3][4];

    #pragma unroll
    for (int c = 0; c < 3; c++) {
        const float* p = base + (long)c * S3;
        float4 c4 = *reinterpret_cast<const float4*>(p + co);
        float4 xm = *reinterpret_cast<const float4*>(p + cxm);
        float4 xp = *reinterpret_cast<const float4*>(p + cxp);
        float4 ym = *reinterpret_cast<const float4*>(p + cym);
        float4 yp = *reinterpret_cast<const float4*>(p + cyp);
        float zprev = (z4 > 0)        ? p[co - 1] : c4.x;
        float znext = (z4 + 4 < DD)   ? p[co + 4] : c4.w;

        float cz[6]  = {zprev, c4.x, c4.y, c4.z, c4.w, znext};
        float xmv[4] = {xm.x, xm.y, xm.z, xm.w};
        float xpv[4] = {xp.x, xp.y, xp.z, xp.w};
        float ymv[4] = {ym.x, ym.y, ym.z, ym.w};
        float ypv[4] = {yp.x, yp.y, yp.z, yp.w};

        #pragma unroll
        for (int j = 0; j < 4; j++) {
            int z = z4 + j;
            float sz = (z == 0 || z == DD-1) ? 1.0f : 0.5f;
            dX[c][j] = (xpv[j] - xmv[j]) * sx;
            dY[c][j] = (ypv[j] - ymv[j]) * sy;
            dZ[c][j] = (cz[j + 2] - cz[j]) * sz;
        }
    }

    float sum = 0.0f;
    #pragma unroll
    for (int j = 0; j < 4; j++) {
        float ux = dX[0][j], uy = dY[0][j], uz = dZ[0][j];
        float vx = dX[1][j], vy = dY[1][j], vz = dZ[1][j];
        float wx = dX[2][j], wy = dY[2][j], wz = dZ[2][j];

        float tr  = ux + vy + wz;
        float exy = 0.5f * (uy + vx);
        float exz = 0.5f * (uz + wx);
        float eyz = 0.5f * (vz + wy);

        float rt  = robust01(tr);
        float rxx = robust01(ux), ryy = robust01(vy), rzz = robust01(wz);
        float rxy = robust01(exy), rxz = robust01(exz), ryz = robust01(eyz);

        // 0.5*LAMBDA*rt^2 + MU*(diag^2 + 2*offdiag^2), LAMBDA=1.0, MU=0.5
        float energy = 0.5f * rt * rt
                     + 0.5f * (rxx * rxx + ryy * ryy + rzz * rzz
                               + 2.0f * (rxy * rxy + rxz * rxz + ryz * ryz));

        float jac = (1.0f + ux) * ((1.0f + vy) * (1.0f + wz) - vz * wy)
                  - uy * (vx * (1.0f + wz) - vz * (1.0f + wx))
                  + uz * (vx * wy - (1.0f + vy) * (1.0f + wx));

        sum += energy + 0.1f * fmaxf(-jac, 0.0f);
    }

    // ---- reduction: warp shfl (double) -> smem -> one atomicAdd per block
    double d = (double)sum;
    #pragma unroll
    for (int o = 16; o > 0; o >>= 1)
        d += __shfl_down_sync(0xffffffffu, d, o);

    __shared__ double ws[6];
    int tid = threadIdx.x + threadIdx.y * 48;   // 192 threads = 6 full warps
    int w = tid >> 5, l = tid & 31;
    if (l == 0) ws[w] = d;
    __syncthreads();
    if (tid == 0) {
        double t = 0.0;
        #pragma unroll
        for (int i = 0; i < 6; i++) t += ws[i];
        atomicAdd(&g_accum, t);
    }
}

__global__ void finalize_kernel(float* out) {
    out[0] = (float)(g_accum / NVOX);
}

extern "C" void kernel_launch(void* const* d_in, const int* in_sizes, int n_in,
                              void* d_out, int out_size) {
    const float* df = (const float*)d_in[0];
    float* out = (float*)d_out;

    zero_kernel<<<1, 1>>>();
    dim3 blk(48, 4);
    int grid = 2 * DD * (DD / 4);   // 18432 blocks
    elastic_kernel<<<grid, blk>>>(df);
    finalize_kernel<<<1, 1>>>(out);
}

// round 6
// speedup vs baseline: 1.7185x; 1.7185x over previous
#include <cuda_runtime.h>
#include <cuda_bf16.h>

// ElasticEnergyLossWithJacobian — GB300 sm_103a, round 5.
// x-sweep with register sliding window: dX from registers; center loaded once
// per byte; y±1 / z-halo loads are L1 hits. Per-block partials, no atomics.

#define DD 192
#define S1 192
#define S2 (192*192)
#define S3 (192*192*192)
#define XSEG 16
#define NSEG (DD / XSEG)          // 12
#define NBLK (2 * NSEG * 48)      // 1152 blocks
#define NVOX (2.0*192.0*192.0*192.0)

__device__ double g_part[NBLK];

__device__ __forceinline__ float robust01(float x) {
    // delta = 0.01
    float a = fabsf(x);
    return (a <= 0.01f) ? 0.5f * x * x : 0.01f * (a - 0.005f);
}

__global__ __launch_bounds__(192) void elastic_kernel(const float* __restrict__ df) {
    int bid   = blockIdx.x;
    int b     = bid / (NSEG * 48);
    int r     = bid % (NSEG * 48);
    int xseg  = r / 48;
    int ytile = r % 48;
    int y  = ytile * 4 + threadIdx.y;   // blockDim = (48, 4)
    int z4 = threadIdx.x * 4;
    int x0 = xseg * XSEG;

    const float* base = df + (size_t)b * 3 * S3;
    int offyz = y * S1 + z4;
    int ymoff = max(y - 1, 0) * S1 + z4;
    int ypoff = min(y + 1, DD - 1) * S1 + z4;

    float sy = (y == 0 || y == DD - 1) ? 1.0f : 0.5f;

    // Register sliding window: planes x-1 (wm) and x (wc) per component.
    float4 wm[3], wc[3];
    {
        int xm = (x0 == 0) ? 0 : x0 - 1;
        #pragma unroll
        for (int c = 0; c < 3; c++) {
            const float* p = base + c * S3;
            wm[c] = *reinterpret_cast<const float4*>(p + xm * S2 + offyz);
            wc[c] = *reinterpret_cast<const float4*>(p + x0 * S2 + offyz);
        }
    }

    float sum0 = 0.0f, sum1 = 0.0f;

    #pragma unroll 2
    for (int xi = 0; xi < XSEG; xi++) {
        int x  = x0 + xi;
        int xn = (x == DD - 1) ? x : x + 1;
        float sx = (x == 0 || x == DD - 1) ? 1.0f : 0.5f;

        int co = x * S2 + offyz;

        float4 wp[3], ym4[3], yp4[3];
        float zm[3], zp[3];
        #pragma unroll
        for (int c = 0; c < 3; c++) {
            const float* p = base + c * S3;
            wp[c]  = *reinterpret_cast<const float4*>(p + xn * S2 + offyz);
            ym4[c] = *reinterpret_cast<const float4*>(p + x * S2 + ymoff);
            yp4[c] = *reinterpret_cast<const float4*>(p + x * S2 + ypoff);
            zm[c] = (z4 > 0)       ? p[co - 1] : wc[c].x;
            zp[c] = (z4 + 4 < DD)  ? p[co + 4] : wc[c].w;
        }

        float dX[3][4], dY[3][4], dZ[3][4];
        #pragma unroll
        for (int c = 0; c < 3; c++) {
            float cz[6]  = {zm[c], wc[c].x, wc[c].y, wc[c].z, wc[c].w, zp[c]};
            float xmv[4] = {wm[c].x, wm[c].y, wm[c].z, wm[c].w};
            float xpv[4] = {wp[c].x, wp[c].y, wp[c].z, wp[c].w};
            float ymv[4] = {ym4[c].x, ym4[c].y, ym4[c].z, ym4[c].w};
            float ypv[4] = {yp4[c].x, yp4[c].y, yp4[c].z, yp4[c].w};
            #pragma unroll
            for (int j = 0; j < 4; j++) {
                int z = z4 + j;
                float sz = (z == 0 || z == DD - 1) ? 1.0f : 0.5f;
                dX[c][j] = (xpv[j] - xmv[j]) * sx;
                dY[c][j] = (ypv[j] - ymv[j]) * sy;
                dZ[c][j] = (cz[j + 2] - cz[j]) * sz;
            }
        }

        #pragma unroll
        for (int j = 0; j < 4; j++) {
            float ux = dX[0][j], uy = dY[0][j], uz = dZ[0][j];
            float vx = dX[1][j], vy = dY[1][j], vz = dZ[1][j];
            float wx = dX[2][j], wy = dY[2][j], wz = dZ[2][j];

            float tr  = ux + vy + wz;
            float exy = 0.5f * (uy + vx);
            float exz = 0.5f * (uz + wx);
            float eyz = 0.5f * (vz + wy);

            float rt  = robust01(tr);
            float rxx = robust01(ux), ryy = robust01(vy), rzz = robust01(wz);
            float rxy = robust01(exy), rxz = robust01(exz), ryz = robust01(eyz);

            // 0.5*LAMBDA*rt^2 + MU*(diag^2 + 2*offdiag^2), LAMBDA=1, MU=0.5
            float energy = 0.5f * rt * rt
                         + 0.5f * (rxx * rxx + ryy * ryy + rzz * rzz
                                   + 2.0f * (rxy * rxy + rxz * rxz + ryz * ryz));

            float jac = (1.0f + ux) * ((1.0f + vy) * (1.0f + wz) - vz * wy)
                      - uy * (vx * (1.0f + wz) - vz * (1.0f + wx))
                      + uz * (vx * wy - (1.0f + vy) * (1.0f + wx));

            float val = energy + 0.1f * fmaxf(-jac, 0.0f);
            if (j & 1) sum1 += val; else sum0 += val;
        }

        // shift window
        #pragma unroll
        for (int c = 0; c < 3; c++) { wm[c] = wc[c]; wc[c] = wp[c]; }
    }

    // ---- block reduction: warp shfl (double) -> smem -> one write per block
    double d = (double)sum0 + (double)sum1;
    #pragma unroll
    for (int o = 16; o > 0; o >>= 1)
        d += __shfl_down_sync(0xffffffffu, d, o);

    __shared__ double ws[6];
    int tid = threadIdx.x + threadIdx.y * 48;   // 192 threads = 6 warps
    int w = tid >> 5, l = tid & 31;
    if (l == 0) ws[w] = d;
    __syncthreads();
    if (tid == 0) {
        double t = 0.0;
        #pragma unroll
        for (int i = 0; i < 6; i++) t += ws[i];
        g_part[bid] = t;    // overwritten every call: deterministic, no zeroing
    }
}

__global__ __launch_bounds__(128) void finalize_kernel(float* out) {
    int tid = threadIdx.x;
    double d = 0.0;
    for (int i = tid; i < NBLK; i += 128) d += g_part[i];
    #pragma unroll
    for (int o = 16; o > 0; o >>= 1)
        d += __shfl_down_sync(0xffffffffu, d, o);
    __shared__ double ws[4];
    if ((tid & 31) == 0) ws[tid >> 5] = d;
    __syncthreads();
    if (tid == 0) {
        double t = ws[0] + ws[1] + ws[2] + ws[3];
        out[0] = (float)(t / NVOX);
    }
}

extern "C" void kernel_launch(void* const* d_in, const int* in_sizes, int n_in,
                              void* d_out, int out_size) {
    const float* df = (const float*)d_in[0];
    float* out = (float*)d_out;

    dim3 blk(48, 4);
    elastic_kernel<<<NBLK, blk>>>(df);
    finalize_kernel<<<1, 128>>>(out);
}